// round 1
// baseline (speedup 1.0000x reference)
#include <cuda_runtime.h>
#include <cstdint>
#include <math.h>

#define BATCH   2048
#define IN_DIM  512
#define NUM_OUT 256

#define BM 64
#define BN 64
#define BK 16
#define NTHREADS 128
#define NSTEPS (IN_DIM / BK)   // 32

typedef unsigned long long ull;

// Precomputed -sigmoid(5*W_raw), transposed to [k][o] and duplicated along o:
// g_wdup[k*512 + 2*o] == g_wdup[k*512 + 2*o + 1] == -sigmoid(5*W_raw[o][k])
// 512*512 floats = 1 MB.
__device__ float g_wdup[IN_DIM * NUM_OUT * 2];

__global__ void precompute_kernel(const float* __restrict__ Wraw) {
    int i = blockIdx.x * blockDim.x + threadIdx.x;   // 0 .. 131071
    if (i < NUM_OUT * IN_DIM) {
        int k = i >> 8;        // i / 256
        int o = i & 255;       // i % 256
        float v = Wraw[o * IN_DIM + k];
        float w = 1.0f / (1.0f + expf(-5.0f * v));
        float2 p; p.x = -w; p.y = -w;
        *reinterpret_cast<float2*>(&g_wdup[k * (2 * NUM_OUT) + 2 * o]) = p;
    }
}

__device__ __forceinline__ ull ffma2(ull a, ull b, ull c) {
    ull d;
    asm("fma.rn.f32x2 %0, %1, %2, %3;" : "=l"(d) : "l"(a), "l"(b), "l"(c));
    return d;
}
__device__ __forceinline__ ull fmul2(ull a, ull b) {
    ull d;
    asm("mul.rn.f32x2 %0, %1, %2;" : "=l"(d) : "l"(a), "l"(b));
    return d;
}
__device__ __forceinline__ void cp_async16(uint32_t smem, const void* gptr) {
    asm volatile("cp.async.cg.shared.global [%0], [%1], 16;" :: "r"(smem), "l"(gptr));
}

// Each CTA computes a 64(M) x 64(N) tile of S. Accumulator packs two M-rows
// per f32x2 register. w/c-free formulation: z = 1 + (-w) * (1 - x) = fma(nw, t, 1).
__global__ void __launch_bounds__(NTHREADS, 1)
logic_kernel(const float* __restrict__ x, float* __restrict__ out) {
    // xs: k-major (1-x) tile, padded stride 68 floats (bank-conflict-free fill,
    // 16B-aligned rows: 68*4 = 272 bytes, 272 % 16 == 0).
    __shared__ __align__(16) float xs[2][BK][68];
    // ws: duplicated -w tile: row k holds 128 floats = 64 cols duplicated.
    __shared__ __align__(16) float ws[2][BK][2 * BN];

    const int tid = threadIdx.x;
    const int bm0 = blockIdx.x * BM;
    const int bn  = blockIdx.y;

    const int tc = tid & 15;   // 16 col-groups of 4 outputs
    const int tr = tid >> 4;   // 8 row-groups of 8 rows

    // x staging mapping: thread handles row xm, k-half xq (8 k's each)
    const int xm = tid & 63;
    const int xq = tid >> 6;   // 0 or 1

    const ull ONE2 = 0x3F8000003F800000ULL;   // (1.0f, 1.0f)
    ull acc[4][4];
#pragma unroll
    for (int i = 0; i < 4; ++i)
#pragma unroll
        for (int j = 0; j < 4; ++j) acc[i][j] = ONE2;

    const float* xrow = x + (ull)(bm0 + xm) * IN_DIM + xq * 8;

    // ---------------- prologue: fill buffer 0 ----------------
    {
        float4 a = *reinterpret_cast<const float4*>(xrow + 0);
        float4 b = *reinterpret_cast<const float4*>(xrow + 4);
#pragma unroll
        for (int c = 0; c < 4; ++c) {
            int idx = c * 128 + tid;
            int k   = idx >> 5;
            int col = idx & 31;
            const float* src = g_wdup + (ull)k * (2 * NUM_OUT) + bn * (2 * BN) + col * 4;
            cp_async16((uint32_t)__cvta_generic_to_shared(&ws[0][k][col * 4]), src);
        }
        asm volatile("cp.async.commit_group;" ::: "memory");
        int kb = xq * 8;
        xs[0][kb + 0][xm] = 1.0f - a.x;
        xs[0][kb + 1][xm] = 1.0f - a.y;
        xs[0][kb + 2][xm] = 1.0f - a.z;
        xs[0][kb + 3][xm] = 1.0f - a.w;
        xs[0][kb + 4][xm] = 1.0f - b.x;
        xs[0][kb + 5][xm] = 1.0f - b.y;
        xs[0][kb + 6][xm] = 1.0f - b.z;
        xs[0][kb + 7][xm] = 1.0f - b.w;
    }

    // ---------------- main loop ----------------
    for (int step = 0; step < NSTEPS; ++step) {
        const int buf  = step & 1;
        const int nbuf = buf ^ 1;
        const bool more = (step + 1 < NSTEPS);

        // bar A: everyone finished compute(step-1) (so nbuf is free to refill)
        // and x STS(step) from last iteration is visible.
        __syncthreads();

        float4 a, b;
        if (more) {
            const float* xp = xrow + (step + 1) * BK;
            a = *reinterpret_cast<const float4*>(xp + 0);
            b = *reinterpret_cast<const float4*>(xp + 4);
            int k0 = (step + 1) * BK;
#pragma unroll
            for (int c = 0; c < 4; ++c) {
                int idx = c * 128 + tid;
                int k   = idx >> 5;
                int col = idx & 31;
                const float* src = g_wdup + (ull)(k0 + k) * (2 * NUM_OUT) + bn * (2 * BN) + col * 4;
                cp_async16((uint32_t)__cvta_generic_to_shared(&ws[nbuf][k][col * 4]), src);
            }
        }
        asm volatile("cp.async.commit_group;" ::: "memory");
        // w(step) complete (at most the step+1 group left pending)
        asm volatile("cp.async.wait_group 1;" ::: "memory");
        // bar B: all threads' cp.asyncs for buf landed -> ws[buf] readable by all
        __syncthreads();

        // ---------- compute on buf ----------
#pragma unroll
        for (int k = 0; k < BK; ++k) {
            ulonglong2 xa = *reinterpret_cast<const ulonglong2*>(&xs[buf][k][tr * 8]);
            ulonglong2 xb = *reinterpret_cast<const ulonglong2*>(&xs[buf][k][tr * 8 + 4]);
            ulonglong2 wa = *reinterpret_cast<const ulonglong2*>(&ws[buf][k][tc * 8]);
            ulonglong2 wb = *reinterpret_cast<const ulonglong2*>(&ws[buf][k][tc * 8 + 4]);
            ull xv[4] = {xa.x, xa.y, xb.x, xb.y};   // pairs of (1-x) for rows 2i,2i+1
            ull wv[4] = {wa.x, wa.y, wb.x, wb.y};   // (-w_j, -w_j) duplicated pairs
#pragma unroll
            for (int j = 0; j < 4; ++j) {
#pragma unroll
                for (int i = 0; i < 4; ++i) {
                    ull z = ffma2(wv[j], xv[i], ONE2);     // (1 - w*t, 1 - w*t)
                    acc[i][j] = fmul2(acc[i][j], z);
                }
            }
        }

        // stage next x tile into nbuf (safe: nbuf not read during compute(step))
        if (more) {
            int kb = xq * 8;
            xs[nbuf][kb + 0][xm] = 1.0f - a.x;
            xs[nbuf][kb + 1][xm] = 1.0f - a.y;
            xs[nbuf][kb + 2][xm] = 1.0f - a.z;
            xs[nbuf][kb + 3][xm] = 1.0f - a.w;
            xs[nbuf][kb + 4][xm] = 1.0f - b.x;
            xs[nbuf][kb + 5][xm] = 1.0f - b.y;
            xs[nbuf][kb + 6][xm] = 1.0f - b.z;
            xs[nbuf][kb + 7][xm] = 1.0f - b.w;
        }
    }

    // ---------------- epilogue ----------------
    float* orow = out + (ull)(bm0 + tr * 8) * NUM_OUT + bn * BN + tc * 4;
#pragma unroll
    for (int r = 0; r < 8; ++r) {
        int i = r >> 1;
        int h = r & 1;
        float4 v;
        v.x = __uint_as_float((unsigned)(acc[i][0] >> (h * 32)));
        v.y = __uint_as_float((unsigned)(acc[i][1] >> (h * 32)));
        v.z = __uint_as_float((unsigned)(acc[i][2] >> (h * 32)));
        v.w = __uint_as_float((unsigned)(acc[i][3] >> (h * 32)));
        *reinterpret_cast<float4*>(orow + (ull)r * NUM_OUT) = v;
    }
}

extern "C" void kernel_launch(void* const* d_in, const int* in_sizes, int n_in,
                              void* d_out, int out_size) {
    const float* x    = (const float*)d_in[0];   // [2048, 512]
    const float* Wraw = (const float*)d_in[1];   // [256, 512]
    float* out        = (float*)d_out;           // [2048, 256]

    precompute_kernel<<<(NUM_OUT * IN_DIM + 255) / 256, 256>>>(Wraw);

    dim3 grid(BATCH / BM, NUM_OUT / BN);         // 32 x 4 = 128 CTAs
    logic_kernel<<<grid, NTHREADS>>>(x, out);
}

// round 2
// speedup vs baseline: 1.1063x; 1.1063x over previous
#include <cuda_runtime.h>
#include <cstdint>
#include <math.h>

#define BATCH   2048
#define IN_DIM  512
#define NUM_OUT 256

#define BM 64
#define BN 64
#define BK 16
#define NTHREADS 128
#define KSPLIT 4
#define KCHUNK (IN_DIM / KSPLIT)     // 128
#define NSTEPS (KCHUNK / BK)         // 8

typedef unsigned long long ull;

// Precomputed -sigmoid(5*W_raw), transposed to [k][o] and duplicated along o:
// g_wdup[k*512 + 2*o] == g_wdup[k*512 + 2*o + 1] == -sigmoid(5*W_raw[o][k])
__device__ float g_wdup[IN_DIM * NUM_OUT * 2];
// Partial products per K-chunk: [KSPLIT][BATCH*NUM_OUT] = 8 MB
__device__ float g_part[KSPLIT][BATCH * NUM_OUT];

__global__ void precompute_kernel(const float* __restrict__ Wraw) {
    int i = blockIdx.x * blockDim.x + threadIdx.x;   // 0 .. 131071
    if (i < NUM_OUT * IN_DIM) {
        int k = i >> 8;        // i / 256
        int o = i & 255;       // i % 256
        float v = Wraw[o * IN_DIM + k];
        float w = 1.0f / (1.0f + __expf(-5.0f * v));
        float2 p; p.x = -w; p.y = -w;
        *reinterpret_cast<float2*>(&g_wdup[k * (2 * NUM_OUT) + 2 * o]) = p;
    }
}

__device__ __forceinline__ ull ffma2(ull a, ull b, ull c) {
    ull d;
    asm("fma.rn.f32x2 %0, %1, %2, %3;" : "=l"(d) : "l"(a), "l"(b), "l"(c));
    return d;
}
__device__ __forceinline__ ull fmul2(ull a, ull b) {
    ull d;
    asm("mul.rn.f32x2 %0, %1, %2;" : "=l"(d) : "l"(a), "l"(b));
    return d;
}
__device__ __forceinline__ void cp_async16(uint32_t smem, const void* gptr) {
    asm volatile("cp.async.cg.shared.global [%0], [%1], 16;" :: "r"(smem), "l"(gptr));
}

// Each CTA computes the partial product over one K-chunk (128 k's) of a
// 64(M) x 64(N) tile. Accumulator packs two M-rows per f32x2 register.
// z = 1 + (-w) * (1 - x) = fma(nw, t, 1).
__global__ void __launch_bounds__(NTHREADS, KSPLIT)
logic_kernel(const float* __restrict__ x) {
    __shared__ __align__(16) float xs[2][BK][68];
    __shared__ __align__(16) float ws[2][BK][2 * BN];

    const int tid = threadIdx.x;
    const int bm0 = blockIdx.x * BM;
    const int bn  = blockIdx.y;
    const int kz  = blockIdx.z;          // K-chunk index
    const int kbase = kz * KCHUNK;

    const int tc = tid & 15;   // 16 col-groups of 4 outputs
    const int tr = tid >> 4;   // 8 row-groups of 8 rows

    const int xm = tid & 63;
    const int xq = tid >> 6;   // 0 or 1

    const ull ONE2 = 0x3F8000003F800000ULL;
    ull acc[4][4];
#pragma unroll
    for (int i = 0; i < 4; ++i)
#pragma unroll
        for (int j = 0; j < 4; ++j) acc[i][j] = ONE2;

    const float* xrow = x + (ull)(bm0 + xm) * IN_DIM + kbase + xq * 8;

    // ---------------- prologue: fill buffer 0 ----------------
    {
        float4 a = *reinterpret_cast<const float4*>(xrow + 0);
        float4 b = *reinterpret_cast<const float4*>(xrow + 4);
#pragma unroll
        for (int c = 0; c < 4; ++c) {
            int idx = c * 128 + tid;
            int k   = idx >> 5;
            int col = idx & 31;
            const float* src = g_wdup + (ull)(kbase + k) * (2 * NUM_OUT) + bn * (2 * BN) + col * 4;
            cp_async16((uint32_t)__cvta_generic_to_shared(&ws[0][k][col * 4]), src);
        }
        asm volatile("cp.async.commit_group;" ::: "memory");
        int kb = xq * 8;
        xs[0][kb + 0][xm] = 1.0f - a.x;
        xs[0][kb + 1][xm] = 1.0f - a.y;
        xs[0][kb + 2][xm] = 1.0f - a.z;
        xs[0][kb + 3][xm] = 1.0f - a.w;
        xs[0][kb + 4][xm] = 1.0f - b.x;
        xs[0][kb + 5][xm] = 1.0f - b.y;
        xs[0][kb + 6][xm] = 1.0f - b.z;
        xs[0][kb + 7][xm] = 1.0f - b.w;
    }

    // ---------------- main loop ----------------
    for (int step = 0; step < NSTEPS; ++step) {
        const int buf  = step & 1;
        const int nbuf = buf ^ 1;
        const bool more = (step + 1 < NSTEPS);

        __syncthreads();   // compute(step-1) done; x STS(step) visible

        float4 a, b;
        if (more) {
            const float* xp = xrow + (step + 1) * BK;
            a = *reinterpret_cast<const float4*>(xp + 0);
            b = *reinterpret_cast<const float4*>(xp + 4);
            int k0 = kbase + (step + 1) * BK;
#pragma unroll
            for (int c = 0; c < 4; ++c) {
                int idx = c * 128 + tid;
                int k   = idx >> 5;
                int col = idx & 31;
                const float* src = g_wdup + (ull)(k0 + k) * (2 * NUM_OUT) + bn * (2 * BN) + col * 4;
                cp_async16((uint32_t)__cvta_generic_to_shared(&ws[nbuf][k][col * 4]), src);
            }
        }
        asm volatile("cp.async.commit_group;" ::: "memory");
        asm volatile("cp.async.wait_group 1;" ::: "memory");
        __syncthreads();   // ws[buf] fully landed

        // ---------- compute on buf ----------
#pragma unroll
        for (int k = 0; k < BK; ++k) {
            ulonglong2 xa = *reinterpret_cast<const ulonglong2*>(&xs[buf][k][tr * 8]);
            ulonglong2 xb = *reinterpret_cast<const ulonglong2*>(&xs[buf][k][tr * 8 + 4]);
            ulonglong2 wa = *reinterpret_cast<const ulonglong2*>(&ws[buf][k][tc * 8]);
            ulonglong2 wb = *reinterpret_cast<const ulonglong2*>(&ws[buf][k][tc * 8 + 4]);
            ull xv[4] = {xa.x, xa.y, xb.x, xb.y};
            ull wv[4] = {wa.x, wa.y, wb.x, wb.y};
#pragma unroll
            for (int j = 0; j < 4; ++j) {
#pragma unroll
                for (int i = 0; i < 4; ++i) {
                    ull z = ffma2(wv[j], xv[i], ONE2);
                    acc[i][j] = fmul2(acc[i][j], z);
                }
            }
        }

        if (more) {
            int kb = xq * 8;
            xs[nbuf][kb + 0][xm] = 1.0f - a.x;
            xs[nbuf][kb + 1][xm] = 1.0f - a.y;
            xs[nbuf][kb + 2][xm] = 1.0f - a.z;
            xs[nbuf][kb + 3][xm] = 1.0f - a.w;
            xs[nbuf][kb + 4][xm] = 1.0f - b.x;
            xs[nbuf][kb + 5][xm] = 1.0f - b.y;
            xs[nbuf][kb + 6][xm] = 1.0f - b.z;
            xs[nbuf][kb + 7][xm] = 1.0f - b.w;
        }
    }

    // ---------------- epilogue: write partial products ----------------
    float* orow = g_part[kz] + (ull)(bm0 + tr * 8) * NUM_OUT + bn * BN + tc * 4;
#pragma unroll
    for (int r = 0; r < 8; ++r) {
        int i = r >> 1;
        int h = r & 1;
        float4 v;
        v.x = __uint_as_float((unsigned)(acc[i][0] >> (h * 32)));
        v.y = __uint_as_float((unsigned)(acc[i][1] >> (h * 32)));
        v.z = __uint_as_float((unsigned)(acc[i][2] >> (h * 32)));
        v.w = __uint_as_float((unsigned)(acc[i][3] >> (h * 32)));
        *reinterpret_cast<float4*>(orow + (ull)r * NUM_OUT) = v;
    }
}

// out = p0 * p1 * p2 * p3 elementwise (float4-vectorized)
__global__ void combine_kernel(float* __restrict__ out) {
    int i = blockIdx.x * blockDim.x + threadIdx.x;   // 0 .. 131071 (float4 groups)
    if (i < (BATCH * NUM_OUT) / 4) {
        float4 a = reinterpret_cast<const float4*>(g_part[0])[i];
        float4 b = reinterpret_cast<const float4*>(g_part[1])[i];
        float4 c = reinterpret_cast<const float4*>(g_part[2])[i];
        float4 d = reinterpret_cast<const float4*>(g_part[3])[i];
        float4 v;
        v.x = (a.x * b.x) * (c.x * d.x);
        v.y = (a.y * b.y) * (c.y * d.y);
        v.z = (a.z * b.z) * (c.z * d.z);
        v.w = (a.w * b.w) * (c.w * d.w);
        reinterpret_cast<float4*>(out)[i] = v;
    }
}

extern "C" void kernel_launch(void* const* d_in, const int* in_sizes, int n_in,
                              void* d_out, int out_size) {
    const float* x    = (const float*)d_in[0];   // [2048, 512]
    const float* Wraw = (const float*)d_in[1];   // [256, 512]
    float* out        = (float*)d_out;           // [2048, 256]

    precompute_kernel<<<(NUM_OUT * IN_DIM + 255) / 256, 256>>>(Wraw);

    dim3 grid(BATCH / BM, NUM_OUT / BN, KSPLIT);   // 32 x 4 x 4 = 512 CTAs
    logic_kernel<<<grid, NTHREADS>>>(x);

    combine_kernel<<<(BATCH * NUM_OUT / 4 + 255) / 256, 256>>>(out);
}